// round 3
// baseline (speedup 1.0000x reference)
#include <cuda_runtime.h>
#include <math.h>

#define N_NODES 100000
#define N_EDGES 1600000
#define HID 64
#define NH (N_NODES * HID)
#define NEG 0.2f
#define SCAN_BLOCKS 98   // ceil(100000/1024)

// ---------------- scratch (static device globals; no runtime alloc) ----------
__device__ float g_xs[NH];          // projected features [N,64]
__device__ float g_xb[NH];          // GAT output (tanh)  [N,64]
__device__ float g_asrc[N_NODES];
__device__ float g_adst[N_NODES];
__device__ int   g_cnt[N_NODES];
__device__ int   g_rowptr[N_NODES + 1];
__device__ int   g_cursor[N_NODES];
__device__ int   g_bsum[SCAN_BLOCKS];
__device__ int   g_boff[SCAN_BLOCKS];
__device__ int   g_csr[N_EDGES];    // src node per CSR slot (grouped by dst)
__device__ float2 g_Wt2[64 * 256];  // k-major interleaved (Wih, Whh): 128KB, L1-resident
__device__ int   g_is64;            // 1 if edge_index marshaled as int64, else int32

// ---------------- edge dtype probe + accessor --------------------------------
// int64 node ids < 100000 have zero high words; int32 data has live odd words.
__global__ void k_detect(const int* __restrict__ eiw) {
    if (blockIdx.x == 0 && threadIdx.x == 0) {
        int odd_zero = 1;
        for (int i = 0; i < 256; i++)
            if (eiw[2 * i + 1] != 0) { odd_zero = 0; break; }
        g_is64 = odd_zero;
    }
}
__device__ __forceinline__ int edge_at(const int* __restrict__ eiw, int idx) {
    // element idx in the logical int array [2*E]; low word if int64 (little-endian)
    return g_is64 ? eiw[2 * idx] : eiw[idx];
}

// ---------------- kernel 1: xs = x @ W,  a_src = xs@att_src, a_dst = xs@att_dst
// blockDim (64,4): 8 rows per block, each thread computes 2 rows x 1 col.
__global__ void k_proj(const float* __restrict__ x, const float* __restrict__ W,
                       const float* __restrict__ att_s, const float* __restrict__ att_d) {
    __shared__ float Wsm[64 * 64];
    __shared__ __align__(16) float xt[8 * 64];
    __shared__ float s1[8][64];
    __shared__ float s2[8][64];
    __shared__ float sa[64], sd[64];

    const int tx = threadIdx.x;          // 0..63 (col)
    const int ty = threadIdx.y;          // 0..3
    const int tid = ty * 64 + tx;        // 0..255
    const int row0 = blockIdx.x * 8;

    for (int i = tid; i < 4096; i += 256) Wsm[i] = W[i];
    for (int i = tid; i < 512; i += 256) xt[i] = x[row0 * 64 + i];
    if (tid < 64) sa[tid] = att_s[tid];
    else if (tid < 128) sd[tid - 64] = att_d[tid - 64];
    __syncthreads();

    const float4* xr0 = (const float4*)&xt[ty * 64];
    const float4* xr1 = (const float4*)&xt[(ty + 4) * 64];
    float acc0 = 0.f, acc1 = 0.f;
    #pragma unroll
    for (int kk = 0; kk < 16; kk++) {
        float4 a = xr0[kk];
        float4 b = xr1[kk];
        float w0 = Wsm[(4 * kk + 0) * 64 + tx];
        float w1 = Wsm[(4 * kk + 1) * 64 + tx];
        float w2 = Wsm[(4 * kk + 2) * 64 + tx];
        float w3 = Wsm[(4 * kk + 3) * 64 + tx];
        acc0 += a.x * w0 + a.y * w1 + a.z * w2 + a.w * w3;
        acc1 += b.x * w0 + b.y * w1 + b.z * w2 + b.w * w3;
    }
    g_xs[(row0 + ty) * 64 + tx]     = acc0;
    g_xs[(row0 + ty + 4) * 64 + tx] = acc1;
    s1[ty][tx]     = acc0 * sa[tx];
    s1[ty + 4][tx] = acc1 * sa[tx];
    s2[ty][tx]     = acc0 * sd[tx];
    s2[ty + 4][tx] = acc1 * sd[tx];
    __syncthreads();
    #pragma unroll
    for (int s = 32; s > 0; s >>= 1) {
        if (tx < s) {
            s1[ty][tx]     += s1[ty][tx + s];
            s1[ty + 4][tx] += s1[ty + 4][tx + s];
            s2[ty][tx]     += s2[ty][tx + s];
            s2[ty + 4][tx] += s2[ty + 4][tx + s];
        }
        __syncthreads();
    }
    if (tx == 0) {
        g_asrc[row0 + ty]     = s1[ty][0];
        g_asrc[row0 + ty + 4] = s1[ty + 4][0];
        g_adst[row0 + ty]     = s2[ty][0];
        g_adst[row0 + ty + 4] = s2[ty + 4][0];
    }
}

// ---------------- CSR build --------------------------------------------------
__global__ void k_zero() {
    int i = blockIdx.x * blockDim.x + threadIdx.x;
    if (i < N_NODES) g_cnt[i] = 0;
}
__global__ void k_count(const int* __restrict__ eiw) {
    int e = blockIdx.x * blockDim.x + threadIdx.x;
    if (e < N_EDGES) {
        int dst = edge_at(eiw, N_EDGES + e);
        if ((unsigned)dst < (unsigned)N_NODES) atomicAdd(&g_cnt[dst], 1);
    }
}
__global__ void k_scan1() {
    __shared__ int sm[1024];
    int i = blockIdx.x * 1024 + threadIdx.x;
    int v = (i < N_NODES) ? g_cnt[i] : 0;
    sm[threadIdx.x] = v;
    __syncthreads();
    for (int off = 1; off < 1024; off <<= 1) {
        int t = 0;
        if ((int)threadIdx.x >= off) t = sm[threadIdx.x - off];
        __syncthreads();
        sm[threadIdx.x] += t;
        __syncthreads();
    }
    if (i < N_NODES) g_rowptr[i] = sm[threadIdx.x] - v;     // block-local exclusive
    if (threadIdx.x == 1023) g_bsum[blockIdx.x] = sm[1023];
}
__global__ void k_scan2() {
    if (threadIdx.x == 0) {
        int s = 0;
        for (int b = 0; b < SCAN_BLOCKS; b++) { g_boff[b] = s; s += g_bsum[b]; }
    }
}
__global__ void k_scan3() {
    int i = blockIdx.x * 1024 + threadIdx.x;
    if (i < N_NODES) {
        int v = g_rowptr[i] + g_boff[blockIdx.x];
        g_rowptr[i] = v;
        g_cursor[i] = v;
    }
    if (i == 0) g_rowptr[N_NODES] = N_EDGES;
}
__global__ void k_fill(const int* __restrict__ eiw) {
    int e = blockIdx.x * blockDim.x + threadIdx.x;
    if (e < N_EDGES) {
        int dst = edge_at(eiw, N_EDGES + e);
        int src = edge_at(eiw, e);
        if ((unsigned)dst < (unsigned)N_NODES && (unsigned)src < (unsigned)N_NODES) {
            int pos = atomicAdd(&g_cursor[dst], 1);
            if ((unsigned)pos < (unsigned)N_EDGES) g_csr[pos] = src;
        }
    }
}

// ---------------- kernel: transpose/interleave LSTM weights ------------------
// g_Wt2[k*256 + g] = (Wih[g][k], Whh[g][k]); Wih/Whh are [256,64] row-major.
__global__ void k_prep(const float* __restrict__ Wih, const float* __restrict__ Whh) {
    int idx = blockIdx.x * 256 + threadIdx.x;   // 0..16383
    int g = idx & 255;
    int k = idx >> 8;
    g_Wt2[idx] = make_float2(Wih[g * 64 + k], Whh[g * 64 + k]);
}

// ---------------- kernel 3: per-node softmax aggregation + tanh --------------
// one warp per destination node; each lane owns 2 of the 64 feature dims.
__global__ void k_agg(const float* __restrict__ bias) {
    const int warp = threadIdx.x >> 5;
    const int lane = threadIdx.x & 31;
    const int node = blockIdx.x * 8 + warp;

    const int start = g_rowptr[node];
    const int deg   = g_rowptr[node + 1] - start;
    const float adst = g_adst[node];

    // pass 1: segment max of leaky_relu attention logits
    float m = -INFINITY;
    for (int k = lane; k < deg; k += 32) {
        int s = g_csr[start + k];
        float e = g_asrc[s] + adst;
        e = fmaxf(e, NEG * e);
        m = fmaxf(m, e);
    }
    #pragma unroll
    for (int o = 16; o; o >>= 1) m = fmaxf(m, __shfl_xor_sync(0xffffffffu, m, o));

    // pass 2: weighted sum with unnormalized p, plus z
    float accx = 0.f, accy = 0.f, z = 0.f;
    for (int base = 0; base < deg; base += 32) {
        int k = base + lane;
        float p = 0.f;
        int s = 0;
        if (k < deg) {
            s = g_csr[start + k];
            float e = g_asrc[s] + adst;
            e = fmaxf(e, NEG * e);
            p = __expf(e - m);
        }
        z += p;
        int cnt = min(32, deg - base);
        for (int j = 0; j < cnt; j++) {
            float pj = __shfl_sync(0xffffffffu, p, j);
            int   sj = __shfl_sync(0xffffffffu, s, j);
            float2 v = *(const float2*)&g_xs[sj * HID + 2 * lane];
            accx += pj * v.x;
            accy += pj * v.y;
        }
    }
    #pragma unroll
    for (int o = 16; o; o >>= 1) z += __shfl_xor_sync(0xffffffffu, z, o);
    float inv = 1.f / (z + 1e-16f);
    float bx = bias[2 * lane], by = bias[2 * lane + 1];
    g_xb[node * HID + 2 * lane]     = tanhf(accx * inv + bx);
    g_xb[node * HID + 2 * lane + 1] = tanhf(accy * inv + by);
}

// ---------------- kernel 4: fused LSTM step + output writes ------------------
// Static SMEM only (12KB). Weights read from g_Wt2 through L1 (128KB resident).
__device__ __forceinline__ float sigf(float v) { return 1.f / (1.f + __expf(-v)); }

__global__ void k_lstm(const float* __restrict__ h_in, const float* __restrict__ c_in,
                       float* __restrict__ out) {
    __shared__ __align__(16) float xbs[512];   // 8 rows x 64
    __shared__ __align__(16) float hs[512];    // 8 rows x 64
    __shared__ float gs[2048];                 // 8 rows x 256 gates

    const int tid = threadIdx.x;               // 256 threads; g = gate column
    const int g = tid;

    for (int rg = blockIdx.x; rg < N_NODES / 8; rg += gridDim.x) {
        const int row0 = rg * 8;
        for (int idx = tid; idx < 512; idx += 256) {
            xbs[idx] = g_xb[row0 * 64 + idx];
            hs[idx]  = h_in[row0 * 64 + idx];
        }
        __syncthreads();

        float acc[8];
        #pragma unroll
        for (int r = 0; r < 8; r++) acc[r] = 0.f;

        const float4* xb4 = (const float4*)xbs;
        const float4* h4  = (const float4*)hs;
        #pragma unroll
        for (int kk = 0; kk < 16; kk++) {
            float2 w0 = g_Wt2[(kk * 4 + 0) * 256 + g];
            float2 w1 = g_Wt2[(kk * 4 + 1) * 256 + g];
            float2 w2 = g_Wt2[(kk * 4 + 2) * 256 + g];
            float2 w3 = g_Wt2[(kk * 4 + 3) * 256 + g];
            #pragma unroll
            for (int r = 0; r < 8; r++) {
                float4 xq = xb4[r * 16 + kk];
                float4 hq = h4[r * 16 + kk];
                acc[r] += xq.x * w0.x + hq.x * w0.y;
                acc[r] += xq.y * w1.x + hq.y * w1.y;
                acc[r] += xq.z * w2.x + hq.z * w2.y;
                acc[r] += xq.w * w3.x + hq.w * w3.y;
            }
        }
        #pragma unroll
        for (int r = 0; r < 8; r++) gs[r * 256 + g] = acc[r];
        __syncthreads();

        // epilogue: torch gate order i,f,g,o
        const int d  = tid & 63;
        const int rr = tid >> 6;        // 0..3
        #pragma unroll
        for (int half = 0; half < 2; half++) {
            int r = rr + half * 4;
            int row = row0 + r;
            float ig = gs[r * 256 + d];
            float fg = gs[r * 256 + 64 + d];
            float gv = gs[r * 256 + 128 + d];
            float og = gs[r * 256 + 192 + d];
            float c0 = c_in[row * 64 + d];
            float c1 = sigf(fg) * c0 + sigf(ig) * tanhf(gv);
            float h1 = sigf(og) * tanhf(c1);
            out[row * 64 + d]          = h1;   // h1 (flat)
            out[NH + row * 64 + d]     = h1;   // h1[None]
            out[2 * NH + row * 64 + d] = c1;   // c1[None]
        }
        __syncthreads();
    }
}

// ---------------- launch -----------------------------------------------------
extern "C" void kernel_launch(void* const* d_in, const int* in_sizes, int n_in,
                              void* d_out, int out_size) {
    const float* x   = (const float*)d_in[0];
    const int*   eiw = (const int*)d_in[1];     // edge_index, dtype-probed on device
    const float* h   = (const float*)d_in[2];
    const float* c   = (const float*)d_in[3];
    const float* Wg  = (const float*)d_in[4];
    const float* as  = (const float*)d_in[5];
    const float* ad  = (const float*)d_in[6];
    const float* bg  = (const float*)d_in[7];
    const float* Wih = (const float*)d_in[8];
    const float* Whh = (const float*)d_in[9];
    float* out = (float*)d_out;

    k_detect<<<1, 32>>>(eiw);
    k_proj<<<N_NODES / 8, dim3(64, 4)>>>(x, Wg, as, ad);
    k_zero<<<(N_NODES + 255) / 256, 256>>>();
    k_count<<<(N_EDGES + 255) / 256, 256>>>(eiw);
    k_prep<<<64, 256>>>(Wih, Whh);
    k_scan1<<<SCAN_BLOCKS, 1024>>>();
    k_scan2<<<1, 32>>>();
    k_scan3<<<SCAN_BLOCKS, 1024>>>();
    k_fill<<<(N_EDGES + 255) / 256, 256>>>(eiw);
    k_agg<<<N_NODES / 8, 256>>>(bg);
    k_lstm<<<296, 256>>>(h, c, out);
}

// round 5
// speedup vs baseline: 1.1509x; 1.1509x over previous
#include <cuda_runtime.h>
#include <math.h>

#define N_NODES 100000
#define N_EDGES 1600000
#define HID 64
#define NH (N_NODES * HID)
#define NEG 0.2f
#define SCAN_BLOCKS 98   // ceil(100000/1024)

// ---------------- scratch (static device globals; no runtime alloc) ----------
__device__ float g_xs[NH];          // projected features [N,64]
__device__ float g_xb[NH];          // GAT output (tanh)  [N,64]
__device__ float g_asrc[N_NODES];
__device__ float g_adst[N_NODES];
__device__ int   g_cnt[N_NODES];
__device__ int   g_rowptr[N_NODES + 1];
__device__ int   g_cursor[N_NODES];
__device__ int   g_bsum[SCAN_BLOCKS];
__device__ int   g_boff[SCAN_BLOCKS];
__device__ int   g_csr[N_EDGES];    // src node per CSR slot (grouped by dst)
__device__ float2 g_Wt2[64 * 256];  // k-major interleaved (Wih, Whh): 128KB, L1-resident
__device__ int   g_is64;            // 1 if edge_index marshaled as int64, else int32

// ---------------- packed f32x2 helpers (Blackwell FFMA2 path) -----------------
__device__ __forceinline__ unsigned long long pk2(float lo, float hi) {
    unsigned long long r;
    asm("mov.b64 %0, {%1, %2};" : "=l"(r) : "f"(lo), "f"(hi));
    return r;
}
__device__ __forceinline__ unsigned long long fma2(unsigned long long a,
                                                   unsigned long long b,
                                                   unsigned long long c) {
    unsigned long long d;
    asm("fma.rn.f32x2 %0, %1, %2, %3;" : "=l"(d) : "l"(a), "l"(b), "l"(c));
    return d;
}
__device__ __forceinline__ float2 up2(unsigned long long v) {
    float2 f;
    asm("mov.b64 {%0, %1}, %2;" : "=f"(f.x), "=f"(f.y) : "l"(v));
    return f;
}

// ---------------- edge dtype probe + accessor --------------------------------
// int64 node ids < 100000 have zero high words; int32 data has live odd words.
__global__ void k_detect(const int* __restrict__ eiw) {
    __shared__ int s_any;
    if (threadIdx.x == 0) s_any = 0;
    __syncthreads();
    if (eiw[2 * threadIdx.x + 1] != 0) s_any = 1;   // benign race
    __syncthreads();
    if (threadIdx.x == 0) g_is64 = (s_any == 0);
}
__device__ __forceinline__ int edge_at(const int* __restrict__ eiw, int idx) {
    return g_is64 ? eiw[2 * idx] : eiw[idx];
}

// ---------------- kernel 1: xs = x @ W,  a_src = xs@att_src, a_dst = xs@att_dst
__global__ void k_proj(const float* __restrict__ x, const float* __restrict__ W,
                       const float* __restrict__ att_s, const float* __restrict__ att_d) {
    __shared__ float Wsm[64 * 64];
    __shared__ __align__(16) float xt[8 * 64];
    __shared__ float s1[8][64];
    __shared__ float s2[8][64];
    __shared__ float sa[64], sd[64];

    const int tx = threadIdx.x;          // 0..63 (col)
    const int ty = threadIdx.y;          // 0..3
    const int tid = ty * 64 + tx;        // 0..255
    const int row0 = blockIdx.x * 8;

    for (int i = tid; i < 4096; i += 256) Wsm[i] = W[i];
    for (int i = tid; i < 512; i += 256) xt[i] = x[row0 * 64 + i];
    if (tid < 64) sa[tid] = att_s[tid];
    else if (tid < 128) sd[tid - 64] = att_d[tid - 64];
    __syncthreads();

    const float4* xr0 = (const float4*)&xt[ty * 64];
    const float4* xr1 = (const float4*)&xt[(ty + 4) * 64];
    float acc0 = 0.f, acc1 = 0.f;
    #pragma unroll
    for (int kk = 0; kk < 16; kk++) {
        float4 a = xr0[kk];
        float4 b = xr1[kk];
        float w0 = Wsm[(4 * kk + 0) * 64 + tx];
        float w1 = Wsm[(4 * kk + 1) * 64 + tx];
        float w2 = Wsm[(4 * kk + 2) * 64 + tx];
        float w3 = Wsm[(4 * kk + 3) * 64 + tx];
        acc0 += a.x * w0 + a.y * w1 + a.z * w2 + a.w * w3;
        acc1 += b.x * w0 + b.y * w1 + b.z * w2 + b.w * w3;
    }
    g_xs[(row0 + ty) * 64 + tx]     = acc0;
    g_xs[(row0 + ty + 4) * 64 + tx] = acc1;
    s1[ty][tx]     = acc0 * sa[tx];
    s1[ty + 4][tx] = acc1 * sa[tx];
    s2[ty][tx]     = acc0 * sd[tx];
    s2[ty + 4][tx] = acc1 * sd[tx];
    __syncthreads();
    #pragma unroll
    for (int s = 32; s > 0; s >>= 1) {
        if (tx < s) {
            s1[ty][tx]     += s1[ty][tx + s];
            s1[ty + 4][tx] += s1[ty + 4][tx + s];
            s2[ty][tx]     += s2[ty][tx + s];
            s2[ty + 4][tx] += s2[ty + 4][tx + s];
        }
        __syncthreads();
    }
    if (tx == 0) {
        g_asrc[row0 + ty]     = s1[ty][0];
        g_asrc[row0 + ty + 4] = s1[ty + 4][0];
        g_adst[row0 + ty]     = s2[ty][0];
        g_adst[row0 + ty + 4] = s2[ty + 4][0];
    }
}

// ---------------- CSR build --------------------------------------------------
__global__ void k_zero() {
    int i = blockIdx.x * blockDim.x + threadIdx.x;
    if (i < N_NODES) g_cnt[i] = 0;
}
__global__ void k_count(const int* __restrict__ eiw) {
    int e = blockIdx.x * blockDim.x + threadIdx.x;
    if (e < N_EDGES) {
        int dst = edge_at(eiw, N_EDGES + e);
        if ((unsigned)dst < (unsigned)N_NODES) atomicAdd(&g_cnt[dst], 1);
    }
}
__global__ void k_scan1() {
    __shared__ int sm[1024];
    int i = blockIdx.x * 1024 + threadIdx.x;
    int v = (i < N_NODES) ? g_cnt[i] : 0;
    sm[threadIdx.x] = v;
    __syncthreads();
    for (int off = 1; off < 1024; off <<= 1) {
        int t = 0;
        if ((int)threadIdx.x >= off) t = sm[threadIdx.x - off];
        __syncthreads();
        sm[threadIdx.x] += t;
        __syncthreads();
    }
    if (i < N_NODES) g_rowptr[i] = sm[threadIdx.x] - v;     // block-local exclusive
    if (threadIdx.x == 1023) g_bsum[blockIdx.x] = sm[1023];
}
__global__ void k_scan2() {
    if (threadIdx.x == 0) {
        int s = 0;
        for (int b = 0; b < SCAN_BLOCKS; b++) { g_boff[b] = s; s += g_bsum[b]; }
    }
}
__global__ void k_scan3() {
    int i = blockIdx.x * 1024 + threadIdx.x;
    if (i < N_NODES) {
        int v = g_rowptr[i] + g_boff[blockIdx.x];
        g_rowptr[i] = v;
        g_cursor[i] = v;
    }
    if (i == 0) g_rowptr[N_NODES] = N_EDGES;
}
__global__ void k_fill(const int* __restrict__ eiw) {
    int e = blockIdx.x * blockDim.x + threadIdx.x;
    if (e < N_EDGES) {
        int dst = edge_at(eiw, N_EDGES + e);
        int src = edge_at(eiw, e);
        if ((unsigned)dst < (unsigned)N_NODES && (unsigned)src < (unsigned)N_NODES) {
            int pos = atomicAdd(&g_cursor[dst], 1);
            if ((unsigned)pos < (unsigned)N_EDGES) g_csr[pos] = src;
        }
    }
}

// ---------------- kernel: transpose/interleave LSTM weights ------------------
__global__ void k_prep(const float* __restrict__ Wih, const float* __restrict__ Whh) {
    int idx = blockIdx.x * 256 + threadIdx.x;   // 0..16383
    int g = idx & 255;
    int k = idx >> 8;
    g_Wt2[idx] = make_float2(Wih[g * 64 + k], Whh[g * 64 + k]);
}

// ---------------- kernel 3: per-node softmax aggregation + tanh --------------
__global__ void k_agg(const float* __restrict__ bias) {
    const int warp = threadIdx.x >> 5;
    const int lane = threadIdx.x & 31;
    const int node = blockIdx.x * 8 + warp;

    const int start = g_rowptr[node];
    const int deg   = g_rowptr[node + 1] - start;
    const float adst = g_adst[node];

    // pass 1: segment max of leaky_relu attention logits
    float m = -INFINITY;
    for (int k = lane; k < deg; k += 32) {
        int s = g_csr[start + k];
        float e = g_asrc[s] + adst;
        e = fmaxf(e, NEG * e);
        m = fmaxf(m, e);
    }
    #pragma unroll
    for (int o = 16; o; o >>= 1) m = fmaxf(m, __shfl_xor_sync(0xffffffffu, m, o));

    // pass 2: weighted sum with unnormalized p, plus z
    unsigned long long acc2 = 0ull;   // packed (accx, accy)
    float z = 0.f;
    for (int base = 0; base < deg; base += 32) {
        int k = base + lane;
        float p = 0.f;
        int s = 0;
        if (k < deg) {
            s = g_csr[start + k];
            float e = g_asrc[s] + adst;
            e = fmaxf(e, NEG * e);
            p = __expf(e - m);
        }
        z += p;
        int cnt = min(32, deg - base);
        for (int j = 0; j < cnt; j++) {
            float pj = __shfl_sync(0xffffffffu, p, j);
            int   sj = __shfl_sync(0xffffffffu, s, j);
            unsigned long long v = *(const unsigned long long*)&g_xs[sj * HID + 2 * lane];
            acc2 = fma2(v, pk2(pj, pj), acc2);
        }
    }
    #pragma unroll
    for (int o = 16; o; o >>= 1) z += __shfl_xor_sync(0xffffffffu, z, o);
    float inv = 1.f / (z + 1e-16f);
    float2 a = up2(acc2);
    float bx = bias[2 * lane], by = bias[2 * lane + 1];
    g_xb[node * HID + 2 * lane]     = tanhf(a.x * inv + bx);
    g_xb[node * HID + 2 * lane + 1] = tanhf(a.y * inv + by);
}

// ---------------- kernel 4: fused LSTM step via packed f32x2 ------------------
// Row tiles stored transposed as [k][pair(row2p,row2p+1)]; acc in packed pairs.
__device__ __forceinline__ float sigf(float v) { return 1.f / (1.f + __expf(-v)); }

__global__ void __launch_bounds__(256) k_lstm(
        const float* __restrict__ h_in, const float* __restrict__ c_in,
        float* __restrict__ out) {
    __shared__ __align__(16) float2 x2t[64 * 4];  // [k][p] = (xb[2p][k], xb[2p+1][k])
    __shared__ __align__(16) float2 h2t[64 * 4];
    __shared__ float gs[2048];                    // 8 rows x 256 gates

    const int tid = threadIdx.x;                  // 256 threads; g = gate column
    const int g = tid;

    for (int rg = blockIdx.x; rg < N_NODES / 8; rg += gridDim.x) {
        const int row0 = rg * 8;
        for (int idx = tid; idx < 512; idx += 256) {
            int r = idx >> 6, k = idx & 63;
            ((float*)&x2t[k * 4 + (r >> 1)])[r & 1] = g_xb[row0 * 64 + idx];
            ((float*)&h2t[k * 4 + (r >> 1)])[r & 1] = h_in[row0 * 64 + idx];
        }
        __syncthreads();

        unsigned long long acc2[4] = {0ull, 0ull, 0ull, 0ull};
        #pragma unroll 8
        for (int k = 0; k < 64; k++) {
            float2 w = g_Wt2[k * 256 + g];
            unsigned long long wih2 = pk2(w.x, w.x);
            unsigned long long whh2 = pk2(w.y, w.y);
            ulonglong2 xa = *(const ulonglong2*)&x2t[k * 4];
            ulonglong2 xb = *(const ulonglong2*)&x2t[k * 4 + 2];
            ulonglong2 ha = *(const ulonglong2*)&h2t[k * 4];
            ulonglong2 hb = *(const ulonglong2*)&h2t[k * 4 + 2];
            acc2[0] = fma2(xa.x, wih2, acc2[0]);
            acc2[1] = fma2(xa.y, wih2, acc2[1]);
            acc2[2] = fma2(xb.x, wih2, acc2[2]);
            acc2[3] = fma2(xb.y, wih2, acc2[3]);
            acc2[0] = fma2(ha.x, whh2, acc2[0]);
            acc2[1] = fma2(ha.y, whh2, acc2[1]);
            acc2[2] = fma2(hb.x, whh2, acc2[2]);
            acc2[3] = fma2(hb.y, whh2, acc2[3]);
        }
        #pragma unroll
        for (int p = 0; p < 4; p++) {
            float2 v = up2(acc2[p]);
            gs[(2 * p)     * 256 + g] = v.x;
            gs[(2 * p + 1) * 256 + g] = v.y;
        }
        __syncthreads();

        // epilogue: torch gate order i,f,g,o
        const int d  = tid & 63;
        const int rr = tid >> 6;        // 0..3
        #pragma unroll
        for (int half = 0; half < 2; half++) {
            int r = rr + half * 4;
            int row = row0 + r;
            float ig = gs[r * 256 + d];
            float fg = gs[r * 256 + 64 + d];
            float gv = gs[r * 256 + 128 + d];
            float og = gs[r * 256 + 192 + d];
            float c0 = c_in[row * 64 + d];
            float c1 = sigf(fg) * c0 + sigf(ig) * tanhf(gv);
            float h1 = sigf(og) * tanhf(c1);
            out[row * 64 + d]          = h1;   // h1 (flat)
            out[NH + row * 64 + d]     = h1;   // h1[None]
            out[2 * NH + row * 64 + d] = c1;   // c1[None]
        }
        __syncthreads();
    }
}

// ---------------- launch -----------------------------------------------------
extern "C" void kernel_launch(void* const* d_in, const int* in_sizes, int n_in,
                              void* d_out, int out_size) {
    const float* x   = (const float*)d_in[0];
    const int*   eiw = (const int*)d_in[1];     // edge_index, dtype-probed on device
    const float* h   = (const float*)d_in[2];
    const float* c   = (const float*)d_in[3];
    const float* Wg  = (const float*)d_in[4];
    const float* as  = (const float*)d_in[5];
    const float* ad  = (const float*)d_in[6];
    const float* bg  = (const float*)d_in[7];
    const float* Wih = (const float*)d_in[8];
    const float* Whh = (const float*)d_in[9];
    float* out = (float*)d_out;

    k_detect<<<1, 256>>>(eiw);
    k_proj<<<N_NODES / 8, dim3(64, 4)>>>(x, Wg, as, ad);
    k_zero<<<(N_NODES + 255) / 256, 256>>>();
    k_count<<<(N_EDGES + 255) / 256, 256>>>(eiw);
    k_prep<<<64, 256>>>(Wih, Whh);
    k_scan1<<<SCAN_BLOCKS, 1024>>>();
    k_scan2<<<1, 32>>>();
    k_scan3<<<SCAN_BLOCKS, 1024>>>();
    k_fill<<<(N_EDGES + 255) / 256, 256>>>(eiw);
    k_agg<<<N_NODES / 8, 256>>>(bg);
    k_lstm<<<592, 256>>>(h, c, out);
}

// round 6
// speedup vs baseline: 1.2575x; 1.0926x over previous
#include <cuda_runtime.h>
#include <math.h>

#define N_NODES 100000
#define N_EDGES 1600000
#define HID 64
#define NH (N_NODES * HID)
#define NEG 0.2f
#define SCAN_BLOCKS 98   // ceil(100000/1024)

// ---------------- scratch (static device globals; no runtime alloc) ----------
__device__ float g_xs[NH];          // projected features [N,64]
__device__ float g_xb[NH];          // GAT output (tanh)  [N,64]
__device__ float g_asrc[N_NODES];
__device__ float g_adst[N_NODES];
__device__ int   g_cnt[N_NODES];
__device__ int   g_rowptr[N_NODES + 1];
__device__ int   g_cursor[N_NODES];
__device__ int   g_bsum[SCAN_BLOCKS];
__device__ int   g_boff[SCAN_BLOCKS];
__device__ int   g_csr[N_EDGES];    // src node per CSR slot (grouped by dst)
__device__ float2 g_Wt2[64 * 256];  // k-major interleaved (Wih, Whh): 128KB, L1-resident
__device__ int   g_is64;            // 1 if edge_index marshaled as int64, else int32

// ---------------- packed f32x2 helpers (Blackwell FFMA2 path) -----------------
__device__ __forceinline__ unsigned long long pk2(float lo, float hi) {
    unsigned long long r;
    asm("mov.b64 %0, {%1, %2};" : "=l"(r) : "f"(lo), "f"(hi));
    return r;
}
__device__ __forceinline__ unsigned long long fma2(unsigned long long a,
                                                   unsigned long long b,
                                                   unsigned long long c) {
    unsigned long long d;
    asm("fma.rn.f32x2 %0, %1, %2, %3;" : "=l"(d) : "l"(a), "l"(b), "l"(c));
    return d;
}
__device__ __forceinline__ float2 up2(unsigned long long v) {
    float2 f;
    asm("mov.b64 {%0, %1}, %2;" : "=f"(f.x), "=f"(f.y) : "l"(v));
    return f;
}

// ---------------- edge dtype probe + accessor --------------------------------
__global__ void k_detect(const int* __restrict__ eiw) {
    __shared__ int s_any;
    if (threadIdx.x == 0) s_any = 0;
    __syncthreads();
    if (eiw[2 * threadIdx.x + 1] != 0) s_any = 1;   // benign race
    __syncthreads();
    if (threadIdx.x == 0) g_is64 = (s_any == 0);
}
__device__ __forceinline__ int edge_at(const int* __restrict__ eiw, int idx) {
    return g_is64 ? eiw[2 * idx] : eiw[idx];
}

// ---------------- kernel 1: xs = x @ W,  a_src, a_dst (shuffle reduction) ----
__global__ void k_proj(const float* __restrict__ x, const float* __restrict__ W,
                       const float* __restrict__ att_s, const float* __restrict__ att_d) {
    __shared__ float Wsm[64 * 64];
    __shared__ __align__(16) float xt[8 * 64];
    __shared__ float part[4][2][4];      // [ty][tx-half][4 partials]

    const int tx = threadIdx.x;          // 0..63 (col)
    const int ty = threadIdx.y;          // 0..3
    const int tid = ty * 64 + tx;        // 0..255
    const int row0 = blockIdx.x * 8;

    for (int i = tid; i < 4096; i += 256) Wsm[i] = W[i];
    for (int i = tid; i < 512; i += 256) xt[i] = x[row0 * 64 + i];
    const float as_v = att_s[tx];
    const float ad_v = att_d[tx];
    __syncthreads();

    const float4* xr0 = (const float4*)&xt[ty * 64];
    const float4* xr1 = (const float4*)&xt[(ty + 4) * 64];
    float acc0 = 0.f, acc1 = 0.f;
    #pragma unroll
    for (int kk = 0; kk < 16; kk++) {
        float4 a = xr0[kk];
        float4 b = xr1[kk];
        float w0 = Wsm[(4 * kk + 0) * 64 + tx];
        float w1 = Wsm[(4 * kk + 1) * 64 + tx];
        float w2 = Wsm[(4 * kk + 2) * 64 + tx];
        float w3 = Wsm[(4 * kk + 3) * 64 + tx];
        acc0 += a.x * w0 + a.y * w1 + a.z * w2 + a.w * w3;
        acc1 += b.x * w0 + b.y * w1 + b.z * w2 + b.w * w3;
    }
    g_xs[(row0 + ty) * 64 + tx]     = acc0;
    g_xs[(row0 + ty + 4) * 64 + tx] = acc1;

    float p0 = acc0 * as_v;   // a_src row ty
    float p1 = acc1 * as_v;   // a_src row ty+4
    float p2 = acc0 * ad_v;   // a_dst row ty
    float p3 = acc1 * ad_v;   // a_dst row ty+4
    #pragma unroll
    for (int o = 16; o; o >>= 1) {
        p0 += __shfl_xor_sync(0xffffffffu, p0, o);
        p1 += __shfl_xor_sync(0xffffffffu, p1, o);
        p2 += __shfl_xor_sync(0xffffffffu, p2, o);
        p3 += __shfl_xor_sync(0xffffffffu, p3, o);
    }
    if ((tx & 31) == 0) {
        int h = tx >> 5;
        part[ty][h][0] = p0; part[ty][h][1] = p1;
        part[ty][h][2] = p2; part[ty][h][3] = p3;
    }
    __syncthreads();
    if (tid < 16) {
        int t = tid & 3, w = tid >> 2;   // w: 0=asrc lo,1=asrc hi,2=adst lo,3=adst hi
        float v = part[t][0][w] + part[t][1][w];
        if (w == 0)      g_asrc[row0 + t]     = v;
        else if (w == 1) g_asrc[row0 + t + 4] = v;
        else if (w == 2) g_adst[row0 + t]     = v;
        else             g_adst[row0 + t + 4] = v;
    }
}

// ---------------- CSR build --------------------------------------------------
__global__ void k_zero() {
    int i = blockIdx.x * blockDim.x + threadIdx.x;
    if (i < N_NODES) g_cnt[i] = 0;
}
__global__ void k_count(const int* __restrict__ eiw) {
    int e = blockIdx.x * blockDim.x + threadIdx.x;
    if (e < N_EDGES) {
        int dst = edge_at(eiw, N_EDGES + e);
        if ((unsigned)dst < (unsigned)N_NODES) atomicAdd(&g_cnt[dst], 1);
    }
}
__global__ void k_scan1() {
    __shared__ int sm[1024];
    int i = blockIdx.x * 1024 + threadIdx.x;
    int v = (i < N_NODES) ? g_cnt[i] : 0;
    sm[threadIdx.x] = v;
    __syncthreads();
    for (int off = 1; off < 1024; off <<= 1) {
        int t = 0;
        if ((int)threadIdx.x >= off) t = sm[threadIdx.x - off];
        __syncthreads();
        sm[threadIdx.x] += t;
        __syncthreads();
    }
    if (i < N_NODES) g_rowptr[i] = sm[threadIdx.x] - v;     // block-local exclusive
    if (threadIdx.x == 1023) g_bsum[blockIdx.x] = sm[1023];
}
__global__ void k_scan2() {
    if (threadIdx.x == 0) {
        int s = 0;
        for (int b = 0; b < SCAN_BLOCKS; b++) { g_boff[b] = s; s += g_bsum[b]; }
    }
}
__global__ void k_scan3() {
    int i = blockIdx.x * 1024 + threadIdx.x;
    if (i < N_NODES) {
        int v = g_rowptr[i] + g_boff[blockIdx.x];
        g_rowptr[i] = v;
        g_cursor[i] = v;
    }
    if (i == 0) g_rowptr[N_NODES] = N_EDGES;
}
__global__ void k_fill(const int* __restrict__ eiw) {
    int e = blockIdx.x * blockDim.x + threadIdx.x;
    if (e < N_EDGES) {
        int dst = edge_at(eiw, N_EDGES + e);
        int src = edge_at(eiw, e);
        if ((unsigned)dst < (unsigned)N_NODES && (unsigned)src < (unsigned)N_NODES) {
            int pos = atomicAdd(&g_cursor[dst], 1);
            if ((unsigned)pos < (unsigned)N_EDGES) g_csr[pos] = src;
        }
    }
}

// ---------------- kernel: transpose/interleave LSTM weights ------------------
__global__ void k_prep(const float* __restrict__ Wih, const float* __restrict__ Whh) {
    int idx = blockIdx.x * 256 + threadIdx.x;   // 0..16383
    int g = idx & 255;
    int k = idx >> 8;
    g_Wt2[idx] = make_float2(Wih[g * 64 + k], Whh[g * 64 + k]);
}

// ---------------- kernel 3: single-pass softmax aggregation + tanh -----------
// Logits are O(few): exp() cannot overflow fp32, so the max-shift is dropped —
// alpha = exp(e)/sum(exp(e)) is mathematically identical to the shifted form.
__global__ void k_agg(const float* __restrict__ bias) {
    const int warp = threadIdx.x >> 5;
    const int lane = threadIdx.x & 31;
    const int node = blockIdx.x * 8 + warp;

    const int start = g_rowptr[node];
    const int deg   = g_rowptr[node + 1] - start;
    const float adst = g_adst[node];

    unsigned long long acc2 = 0ull;   // packed (accx, accy)
    float z = 0.f;
    for (int base = 0; base < deg; base += 32) {
        int k = base + lane;
        float p = 0.f;
        int s = 0;
        if (k < deg) {
            s = g_csr[start + k];
            float e = g_asrc[s] + adst;
            e = fmaxf(e, NEG * e);
            p = __expf(e);
        }
        z += p;
        int cnt = min(32, deg - base);
        for (int j = 0; j < cnt; j += 2) {
            float pj0 = __shfl_sync(0xffffffffu, p, j);
            int   sj0 = __shfl_sync(0xffffffffu, s, j);
            float pj1 = __shfl_sync(0xffffffffu, p, j + 1);
            int   sj1 = __shfl_sync(0xffffffffu, s, j + 1);
            unsigned long long v0 = *(const unsigned long long*)&g_xs[sj0 * HID + 2 * lane];
            acc2 = fma2(v0, pk2(pj0, pj0), acc2);
            if (j + 1 < cnt) {
                unsigned long long v1 = *(const unsigned long long*)&g_xs[sj1 * HID + 2 * lane];
                acc2 = fma2(v1, pk2(pj1, pj1), acc2);
            }
        }
    }
    #pragma unroll
    for (int o = 16; o; o >>= 1) z += __shfl_xor_sync(0xffffffffu, z, o);
    float inv = 1.f / (z + 1e-16f);
    float2 a = up2(acc2);
    float bx = bias[2 * lane], by = bias[2 * lane + 1];
    g_xb[node * HID + 2 * lane]     = tanhf(a.x * inv + bx);
    g_xb[node * HID + 2 * lane + 1] = tanhf(a.y * inv + by);
}

// ---------------- kernel 4: fused LSTM step via packed f32x2, 16-row tiles ---
__device__ __forceinline__ float sigf(float v) { return 1.f / (1.f + __expf(-v)); }

__global__ void __launch_bounds__(256) k_lstm(
        const float* __restrict__ h_in, const float* __restrict__ c_in,
        float* __restrict__ out) {
    __shared__ __align__(16) float2 x2t[64 * 8];  // [k][p] = (xb[2p][k], xb[2p+1][k])
    __shared__ __align__(16) float2 h2t[64 * 8];
    __shared__ float gs[4096];                    // 16 rows x 256 gates

    const int tid = threadIdx.x;                  // 256 threads; g = gate column
    const int g = tid;

    for (int rg = blockIdx.x; rg < N_NODES / 16; rg += gridDim.x) {
        const int row0 = rg * 16;
        for (int idx = tid; idx < 1024; idx += 256) {
            int r = idx >> 6, k = idx & 63;
            ((float*)&x2t[k * 8 + (r >> 1)])[r & 1] = g_xb[row0 * 64 + idx];
            ((float*)&h2t[k * 8 + (r >> 1)])[r & 1] = h_in[row0 * 64 + idx];
        }
        __syncthreads();

        unsigned long long acc2[8];
        #pragma unroll
        for (int p = 0; p < 8; p++) acc2[p] = 0ull;

        #pragma unroll 4
        for (int k = 0; k < 64; k++) {
            float2 w = g_Wt2[k * 256 + g];
            unsigned long long wih2 = pk2(w.x, w.x);
            unsigned long long whh2 = pk2(w.y, w.y);
            const ulonglong2* xk = (const ulonglong2*)&x2t[k * 8];
            const ulonglong2* hk = (const ulonglong2*)&h2t[k * 8];
            #pragma unroll
            for (int q = 0; q < 4; q++) {
                ulonglong2 xv = xk[q];
                ulonglong2 hv = hk[q];
                acc2[2 * q]     = fma2(xv.x, wih2, acc2[2 * q]);
                acc2[2 * q + 1] = fma2(xv.y, wih2, acc2[2 * q + 1]);
                acc2[2 * q]     = fma2(hv.x, whh2, acc2[2 * q]);
                acc2[2 * q + 1] = fma2(hv.y, whh2, acc2[2 * q + 1]);
            }
        }
        #pragma unroll
        for (int p = 0; p < 8; p++) {
            float2 v = up2(acc2[p]);
            gs[(2 * p)     * 256 + g] = v.x;
            gs[(2 * p + 1) * 256 + g] = v.y;
        }
        __syncthreads();

        // epilogue: torch gate order i,f,g,o
        const int d  = tid & 63;
        const int rr = tid >> 6;        // 0..3
        #pragma unroll
        for (int half = 0; half < 4; half++) {
            int r = rr + half * 4;
            int row = row0 + r;
            float ig = gs[r * 256 + d];
            float fg = gs[r * 256 + 64 + d];
            float gv = gs[r * 256 + 128 + d];
            float og = gs[r * 256 + 192 + d];
            float c0 = c_in[row * 64 + d];
            float c1 = sigf(fg) * c0 + sigf(ig) * tanhf(gv);
            float h1 = sigf(og) * tanhf(c1);
            out[row * 64 + d]          = h1;   // h1 (flat)
            out[NH + row * 64 + d]     = h1;   // h1[None]
            out[2 * NH + row * 64 + d] = c1;   // c1[None]
        }
        __syncthreads();
    }
}

// ---------------- launch -----------------------------------------------------
extern "C" void kernel_launch(void* const* d_in, const int* in_sizes, int n_in,
                              void* d_out, int out_size) {
    const float* x   = (const float*)d_in[0];
    const int*   eiw = (const int*)d_in[1];     // edge_index, dtype-probed on device
    const float* h   = (const float*)d_in[2];
    const float* c   = (const float*)d_in[3];
    const float* Wg  = (const float*)d_in[4];
    const float* as  = (const float*)d_in[5];
    const float* ad  = (const float*)d_in[6];
    const float* bg  = (const float*)d_in[7];
    const float* Wih = (const float*)d_in[8];
    const float* Whh = (const float*)d_in[9];
    float* out = (float*)d_out;

    k_detect<<<1, 256>>>(eiw);
    k_proj<<<N_NODES / 8, dim3(64, 4)>>>(x, Wg, as, ad);
    k_zero<<<(N_NODES + 255) / 256, 256>>>();
    k_count<<<(N_EDGES + 255) / 256, 256>>>(eiw);
    k_prep<<<64, 256>>>(Wih, Whh);
    k_scan1<<<SCAN_BLOCKS, 1024>>>();
    k_scan2<<<1, 32>>>();
    k_scan3<<<SCAN_BLOCKS, 1024>>>();
    k_fill<<<(N_EDGES + 255) / 256, 256>>>(eiw);
    k_agg<<<N_NODES / 8, 256>>>(bg);
    k_lstm<<<592, 256>>>(h, c, out);
}

// round 8
// speedup vs baseline: 1.5231x; 1.2112x over previous
#include <cuda_runtime.h>
#include <cuda_fp16.h>
#include <mma.h>
#include <math.h>
#include <stdint.h>

using namespace nvcuda;

#define N_NODES 100000
#define N_EDGES 1600000
#define HID 64
#define NH (N_NODES * HID)
#define NEG 0.2f
#define SCAN_BLOCKS 98   // ceil(100000/1024)

#define TILE_M 128
#define N_TILES 782      // ceil(100000/128)

// LSTM tensor-kernel smem layout
#define LDA 136                          // halves per A row (pad 8)
#define LDG 260                          // floats per gate row (pad 4)
#define SM_A_BYTES (128 * LDA * 2)       // 34816
#define SM_G_BYTES (128 * LDG * 4)       // 133120
#define SM_TOTAL (SM_A_BYTES + SM_G_BYTES)

// ---------------- scratch (static device globals; no runtime alloc) ----------
__device__ float g_xs[NH];          // projected features [N,64]
__device__ float g_xb[NH];          // GAT output (tanh)  [N,64]
__device__ float g_asrc[N_NODES];
__device__ float g_adst[N_NODES];
__device__ int   g_cnt[N_NODES];
__device__ int   g_rowptr[N_NODES + 1];
__device__ int   g_cursor[N_NODES];
__device__ int   g_bsum[SCAN_BLOCKS];
__device__ int   g_boff[SCAN_BLOCKS];
__device__ int   g_csr[N_EDGES];    // src node per CSR slot (grouped by dst)
__device__ int   g_is64;            // 1 if edge_index marshaled as int64, else int32
// fp16 B = [Wih | Whh] row-major [256 gates][128 k]  (64KB, L1/L2 resident)
__device__ __align__(16) __half g_Bh16[256 * 128];

// ---------------- packed f32x2 helpers ---------------------------------------
__device__ __forceinline__ unsigned long long pk2(float lo, float hi) {
    unsigned long long r;
    asm("mov.b64 %0, {%1, %2};" : "=l"(r) : "f"(lo), "f"(hi));
    return r;
}
__device__ __forceinline__ unsigned long long fma2(unsigned long long a,
                                                   unsigned long long b,
                                                   unsigned long long c) {
    unsigned long long d;
    asm("fma.rn.f32x2 %0, %1, %2, %3;" : "=l"(d) : "l"(a), "l"(b), "l"(c));
    return d;
}
__device__ __forceinline__ float2 up2(unsigned long long v) {
    float2 f;
    asm("mov.b64 {%0, %1}, %2;" : "=f"(f.x), "=f"(f.y) : "l"(v));
    return f;
}

// ---------------- edge dtype probe + accessor --------------------------------
__global__ void k_detect(const int* __restrict__ eiw) {
    __shared__ int s_any;
    if (threadIdx.x == 0) s_any = 0;
    __syncthreads();
    if (eiw[2 * threadIdx.x + 1] != 0) s_any = 1;   // benign race
    __syncthreads();
    if (threadIdx.x == 0) g_is64 = (s_any == 0);
}
__device__ __forceinline__ int edge_at(const int* __restrict__ eiw, int idx) {
    return g_is64 ? eiw[2 * idx] : eiw[idx];
}

// ---------------- kernel 1: xs = x @ W,  a_src, a_dst (shuffle reduction) ----
__global__ void k_proj(const float* __restrict__ x, const float* __restrict__ W,
                       const float* __restrict__ att_s, const float* __restrict__ att_d) {
    __shared__ float Wsm[64 * 64];
    __shared__ __align__(16) float xt[8 * 64];
    __shared__ float part[4][2][4];

    const int tx = threadIdx.x;          // 0..63 (col)
    const int ty = threadIdx.y;          // 0..3
    const int tid = ty * 64 + tx;        // 0..255
    const int row0 = blockIdx.x * 8;

    for (int i = tid; i < 4096; i += 256) Wsm[i] = W[i];
    for (int i = tid; i < 512; i += 256) xt[i] = x[row0 * 64 + i];
    const float as_v = att_s[tx];
    const float ad_v = att_d[tx];
    __syncthreads();

    const float4* xr0 = (const float4*)&xt[ty * 64];
    const float4* xr1 = (const float4*)&xt[(ty + 4) * 64];
    float acc0 = 0.f, acc1 = 0.f;
    #pragma unroll
    for (int kk = 0; kk < 16; kk++) {
        float4 a = xr0[kk];
        float4 b = xr1[kk];
        float w0 = Wsm[(4 * kk + 0) * 64 + tx];
        float w1 = Wsm[(4 * kk + 1) * 64 + tx];
        float w2 = Wsm[(4 * kk + 2) * 64 + tx];
        float w3 = Wsm[(4 * kk + 3) * 64 + tx];
        acc0 += a.x * w0 + a.y * w1 + a.z * w2 + a.w * w3;
        acc1 += b.x * w0 + b.y * w1 + b.z * w2 + b.w * w3;
    }
    g_xs[(row0 + ty) * 64 + tx]     = acc0;
    g_xs[(row0 + ty + 4) * 64 + tx] = acc1;

    float p0 = acc0 * as_v;
    float p1 = acc1 * as_v;
    float p2 = acc0 * ad_v;
    float p3 = acc1 * ad_v;
    #pragma unroll
    for (int o = 16; o; o >>= 1) {
        p0 += __shfl_xor_sync(0xffffffffu, p0, o);
        p1 += __shfl_xor_sync(0xffffffffu, p1, o);
        p2 += __shfl_xor_sync(0xffffffffu, p2, o);
        p3 += __shfl_xor_sync(0xffffffffu, p3, o);
    }
    if ((tx & 31) == 0) {
        int hh = tx >> 5;
        part[ty][hh][0] = p0; part[ty][hh][1] = p1;
        part[ty][hh][2] = p2; part[ty][hh][3] = p3;
    }
    __syncthreads();
    if (tid < 16) {
        int t = tid & 3, w = tid >> 2;
        float v = part[t][0][w] + part[t][1][w];
        if (w == 0)      g_asrc[row0 + t]     = v;
        else if (w == 1) g_asrc[row0 + t + 4] = v;
        else if (w == 2) g_adst[row0 + t]     = v;
        else             g_adst[row0 + t + 4] = v;
    }
}

// ---------------- CSR build --------------------------------------------------
__global__ void k_zero() {
    int i = blockIdx.x * blockDim.x + threadIdx.x;
    if (i < N_NODES) g_cnt[i] = 0;
}
__global__ void k_count(const int* __restrict__ eiw) {
    int e = blockIdx.x * blockDim.x + threadIdx.x;
    if (e < N_EDGES) {
        int dst = edge_at(eiw, N_EDGES + e);
        if ((unsigned)dst < (unsigned)N_NODES) atomicAdd(&g_cnt[dst], 1);
    }
}
__global__ void k_scan1() {
    __shared__ int sm[1024];
    int i = blockIdx.x * 1024 + threadIdx.x;
    int v = (i < N_NODES) ? g_cnt[i] : 0;
    sm[threadIdx.x] = v;
    __syncthreads();
    for (int off = 1; off < 1024; off <<= 1) {
        int t = 0;
        if ((int)threadIdx.x >= off) t = sm[threadIdx.x - off];
        __syncthreads();
        sm[threadIdx.x] += t;
        __syncthreads();
    }
    if (i < N_NODES) g_rowptr[i] = sm[threadIdx.x] - v;
    if (threadIdx.x == 1023) g_bsum[blockIdx.x] = sm[1023];
}
__global__ void k_scan2() {
    if (threadIdx.x == 0) {
        int s = 0;
        for (int b = 0; b < SCAN_BLOCKS; b++) { g_boff[b] = s; s += g_bsum[b]; }
    }
}
__global__ void k_scan3() {
    int i = blockIdx.x * 1024 + threadIdx.x;
    if (i < N_NODES) {
        int v = g_rowptr[i] + g_boff[blockIdx.x];
        g_rowptr[i] = v;
        g_cursor[i] = v;
    }
    if (i == 0) g_rowptr[N_NODES] = N_EDGES;
}
__global__ void k_fill(const int* __restrict__ eiw) {
    int e = blockIdx.x * blockDim.x + threadIdx.x;
    if (e < N_EDGES) {
        int dst = edge_at(eiw, N_EDGES + e);
        int src = edge_at(eiw, e);
        if ((unsigned)dst < (unsigned)N_NODES && (unsigned)src < (unsigned)N_NODES) {
            int pos = atomicAdd(&g_cursor[dst], 1);
            if ((unsigned)pos < (unsigned)N_EDGES) g_csr[pos] = src;
        }
    }
}

// ---------------- kernel: build fp16 B = [Wih | Whh], row-major [256][128] ---
__global__ void k_prep(const float* __restrict__ Wih, const float* __restrict__ Whh) {
    int idx = blockIdx.x * 256 + threadIdx.x;   // 0..32767
    int g = idx >> 7;
    int k = idx & 127;
    float v = (k < 64) ? Wih[g * 64 + k] : Whh[g * 64 + (k - 64)];
    g_Bh16[idx] = __float2half_rn(v);
}

// ---------------- kernel 3: single-pass softmax aggregation + tanh -----------
__global__ void k_agg(const float* __restrict__ bias) {
    const int warp = threadIdx.x >> 5;
    const int lane = threadIdx.x & 31;
    const int node = blockIdx.x * 8 + warp;

    const int start = g_rowptr[node];
    const int deg   = g_rowptr[node + 1] - start;
    const float adst = g_adst[node];

    unsigned long long accA = 0ull, accB = 0ull;  // dual accumulators for ILP
    float z = 0.f;
    for (int base = 0; base < deg; base += 32) {
        int k = base + lane;
        float p = 0.f;
        int s = 0;
        if (k < deg) {
            s = g_csr[start + k];
            float e = g_asrc[s] + adst;
            e = fmaxf(e, NEG * e);
            p = __expf(e);
        }
        z += p;
        int cnt = min(32, deg - base);
        for (int j = 0; j < cnt; j += 2) {
            float pj0 = __shfl_sync(0xffffffffu, p, j);
            int   sj0 = __shfl_sync(0xffffffffu, s, j);
            float pj1 = __shfl_sync(0xffffffffu, p, j + 1);
            int   sj1 = __shfl_sync(0xffffffffu, s, j + 1);
            unsigned long long v0 = *(const unsigned long long*)&g_xs[sj0 * HID + 2 * lane];
            accA = fma2(v0, pk2(pj0, pj0), accA);
            if (j + 1 < cnt) {
                unsigned long long v1 = *(const unsigned long long*)&g_xs[sj1 * HID + 2 * lane];
                accB = fma2(v1, pk2(pj1, pj1), accB);
            }
        }
    }
    #pragma unroll
    for (int o = 16; o; o >>= 1) z += __shfl_xor_sync(0xffffffffu, z, o);
    float inv = 1.f / (z + 1e-16f);
    float2 a = up2(accA);
    float2 b = up2(accB);
    float bx = bias[2 * lane], by = bias[2 * lane + 1];
    g_xb[node * HID + 2 * lane]     = tanhf((a.x + b.x) * inv + bx);
    g_xb[node * HID + 2 * lane + 1] = tanhf((a.y + b.y) * inv + by);
}

// ---------------- kernel 4: WMMA fp16 LSTM step ------------------------------
// One CTA per 128-row tile; 16 warps = 4(M) x 4(N).
// Gates[128,256] = A[128,128] x B[256,128]^T, A=[xb|h] fp16, fp32 accumulate.
__device__ __forceinline__ float sigf(float v) { return 1.f / (1.f + __expf(-v)); }

__global__ void __launch_bounds__(512, 1) k_lstm_wmma(
        const float* __restrict__ h_in, const float* __restrict__ c_in,
        float* __restrict__ out) {
    extern __shared__ unsigned char sm_raw[];
    __half* Asm = (__half*)sm_raw;                       // [128][LDA]
    float*  Gsm = (float*)(sm_raw + SM_A_BYTES);         // [128][LDG]

    const int tid = threadIdx.x;
    const int wid = tid >> 5;
    const int row0 = blockIdx.x * TILE_M;

    // --- stage A: fp32 -> fp16 (xb cols 0..63, h cols 64..127) ---
    for (int idx = tid; idx < 8192; idx += 512) {        // half2 granules
        int row = idx >> 6;                              // 0..127
        int k = (idx & 63) * 2;                          // 0..126
        int grow = row0 + row;
        float2 f = make_float2(0.f, 0.f);
        if (grow < N_NODES) {
            f = (k < 64) ? *(const float2*)&g_xb[grow * 64 + k]
                         : *(const float2*)&h_in[grow * 64 + (k - 64)];
        }
        *(__half2*)&Asm[row * LDA + k] = __floats2half2_rn(f.x, f.y);
    }
    __syncthreads();

    // --- MMA: each warp 32 rows x 64 gates ---
    {
        const int wm = wid & 3;       // row tile: rows wm*32 .. +31
        const int wn = wid >> 2;      // gate tile: gates wn*64 .. +63
        wmma::fragment<wmma::accumulator, 16, 16, 16, float> acc[2][4];
        #pragma unroll
        for (int i = 0; i < 2; i++)
            #pragma unroll
            for (int j = 0; j < 4; j++)
                wmma::fill_fragment(acc[i][j], 0.f);

        #pragma unroll
        for (int kk = 0; kk < 8; kk++) {
            wmma::fragment<wmma::matrix_a, 16, 16, 16, __half, wmma::row_major> a[2];
            #pragma unroll
            for (int i = 0; i < 2; i++)
                wmma::load_matrix_sync(a[i], Asm + (wm * 32 + i * 16) * LDA + kk * 16, LDA);
            #pragma unroll
            for (int j = 0; j < 4; j++) {
                // B row-major [gate][k] == col-major (k x n) with col stride 128
                wmma::fragment<wmma::matrix_b, 16, 16, 16, __half, wmma::col_major> b;
                wmma::load_matrix_sync(b, g_Bh16 + (wn * 64 + j * 16) * 128 + kk * 16, 128);
                wmma::mma_sync(acc[0][j], a[0], b, acc[0][j]);
                wmma::mma_sync(acc[1][j], a[1], b, acc[1][j]);
            }
        }
        #pragma unroll
        for (int i = 0; i < 2; i++)
            #pragma unroll
            for (int j = 0; j < 4; j++)
                wmma::store_matrix_sync(Gsm + (wm * 32 + i * 16) * LDG + wn * 64 + j * 16,
                                        acc[i][j], LDG, wmma::mem_row_major);
    }
    __syncthreads();

    // --- epilogue: torch gate order i,f,g,o ---
    const int row = tid >> 2;           // 0..127
    const int q = tid & 3;              // 16-dim group
    const int grow = row0 + row;
    if (grow < N_NODES) {
        const float* grow_g = Gsm + row * LDG;
        #pragma unroll
        for (int v4 = 0; v4 < 4; v4++) {
            int d = q * 16 + v4 * 4;
            float4 c0 = *(const float4*)&c_in[grow * 64 + d];
            float4 hv, cv;
            #pragma unroll
            for (int t = 0; t < 4; t++) {
                float ig = grow_g[d + t];
                float fg = grow_g[64 + d + t];
                float gv = grow_g[128 + d + t];
                float og = grow_g[192 + d + t];
                float c0v = (&c0.x)[t];
                float c1 = sigf(fg) * c0v + sigf(ig) * tanhf(gv);
                float h1 = sigf(og) * tanhf(c1);
                (&hv.x)[t] = h1;
                (&cv.x)[t] = c1;
            }
            *(float4*)&out[grow * 64 + d]          = hv;   // h1 flat
            *(float4*)&out[NH + grow * 64 + d]     = hv;   // h1[None]
            *(float4*)&out[2 * NH + grow * 64 + d] = cv;   // c1[None]
        }
    }
}

// ---------------- launch -----------------------------------------------------
extern "C" void kernel_launch(void* const* d_in, const int* in_sizes, int n_in,
                              void* d_out, int out_size) {
    const float* x   = (const float*)d_in[0];
    const int*   eiw = (const int*)d_in[1];     // edge_index, dtype-probed on device
    const float* h   = (const float*)d_in[2];
    const float* c   = (const float*)d_in[3];
    const float* Wg  = (const float*)d_in[4];
    const float* as  = (const float*)d_in[5];
    const float* ad  = (const float*)d_in[6];
    const float* bg  = (const float*)d_in[7];
    const float* Wih = (const float*)d_in[8];
    const float* Whh = (const float*)d_in[9];
    float* out = (float*)d_out;

    cudaFuncSetAttribute(k_lstm_wmma, cudaFuncAttributeMaxDynamicSharedMemorySize, SM_TOTAL);

    k_detect<<<1, 256>>>(eiw);
    k_proj<<<N_NODES / 8, dim3(64, 4)>>>(x, Wg, as, ad);
    k_zero<<<(N_NODES + 255) / 256, 256>>>();
    k_count<<<(N_EDGES + 255) / 256, 256>>>(eiw);
    k_prep<<<128, 256>>>(Wih, Whh);
    k_scan1<<<SCAN_BLOCKS, 1024>>>();
    k_scan2<<<1, 32>>>();
    k_scan3<<<SCAN_BLOCKS, 1024>>>();
    k_fill<<<(N_EDGES + 255) / 256, 256>>>(eiw);
    k_agg<<<N_NODES / 8, 256>>>(bg);
    k_lstm_wmma<<<N_TILES, 512, SM_TOTAL>>>(h, c, out);
}